// round 2
// baseline (speedup 1.0000x reference)
#include <cuda_runtime.h>
#include <math.h>

// ---------------------------------------------------------------------------
// TFNO4D encoder. Domain after padding: 32^4, channels 32.
// Spectral conv uses only frequencies Klist = {0..7, 24..31} in x,y,z and
// kt = 0..7 in t (rfft). We compute partial DFTs as contraction chains.
// ---------------------------------------------------------------------------

#define NSITE3 32768u    // 32^3
#define NSITE4 1048576u  // 32^4

// Static scratch (allowed per harness rules; no dynamic allocation).
__device__ float  g_bufA[32u * NSITE4];                 // 134 MB
__device__ float  g_bufB[32u * NSITE4];                 // 134 MB
__device__ float2 g_c1[32u * NSITE3 * 8u];              // [C][X][Y][Z][8]   67 MB
__device__ float2 g_c2[32u * 32u * 32u * 16u * 8u];     // [C][X][Y][16][8]  33.5 MB
__device__ float2 g_c3[32u * 32u * 16u * 16u * 8u];     // [C][X][16][16][8] 16.8 MB
__device__ float2 g_c4[32u * 16u * 16u * 16u * 8u];     // [C][16][16][16][8] 8.4 MB
__device__ float2 g_c5[32u * 16u * 16u * 16u * 8u];     // mixed modes        8.4 MB

// Twiddle tables
__device__ float2 g_Wf[16 * 32];   // forward x/y/z: exp(-2pi i k n/32), k in Klist
__device__ float2 g_Wt[8 * 32];    // forward t:     exp(-2pi i k n/32), k=0..7
__device__ float2 g_Wi[32 * 16];   // inverse x/y/z: exp(+2pi i k n/32)
__device__ float  g_ct[32 * 8];    // inverse-t real: f_k * cos(2pi k t/32), f_0=1, f_k=2
__device__ float  g_st[32 * 8];    // inverse-t real: f_k * sin(2pi k t/32)

__device__ __forceinline__ float gelu_exact(float v) {
    return 0.5f * v * (1.0f + erff(v * 0.70710678118654752f));
}

// ---------------------------------------------------------------------------
__global__ void init_tables() {
    int tid = threadIdx.x;
    const float STEP = 6.283185307179586f / 32.0f;
    for (int idx = tid; idx < 16 * 32; idx += blockDim.x) {
        int a = idx >> 5, n = idx & 31;
        int k = (a < 8) ? a : (a + 16);
        float ang = STEP * (float)((k * n) & 31);
        g_Wf[idx] = make_float2(cosf(ang), -sinf(ang));
    }
    for (int idx = tid; idx < 8 * 32; idx += blockDim.x) {
        int k = idx >> 5, n = idx & 31;
        float ang = STEP * (float)((k * n) & 31);
        g_Wt[idx] = make_float2(cosf(ang), -sinf(ang));
    }
    for (int idx = tid; idx < 32 * 16; idx += blockDim.x) {
        int n = idx >> 4, a = idx & 15;
        int k = (a < 8) ? a : (a + 16);
        float ang = STEP * (float)((k * n) & 31);
        g_Wi[idx] = make_float2(cosf(ang), sinf(ang));
    }
    for (int idx = tid; idx < 32 * 8; idx += blockDim.x) {
        int t = idx >> 3, k = idx & 7;
        float f = (k == 0) ? 1.0f : 2.0f;
        float ang = STEP * (float)((k * t) & 31);
        g_ct[idx] = f * cosf(ang);
        g_st[idx] = f * sinf(ang);
    }
}

// ---------------------------------------------------------------------------
// Lift: coords + input -> FC(7->16) -> GELU -> FC(16->32), zero outside 24^4.
__global__ void lift_kernel(const float* __restrict__ x,
                            const float* __restrict__ lw1, const float* __restrict__ lb1,
                            const float* __restrict__ lw2, const float* __restrict__ lb2) {
    __shared__ float w1[16 * 7], b1[16], w2[32 * 16], b2[32];
    int tid = threadIdx.x;
    for (int i = tid; i < 112; i += 256) w1[i] = lw1[i];
    for (int i = tid; i < 16; i += 256) b1[i] = lb1[i];
    for (int i = tid; i < 512; i += 256) w2[i] = lw2[i];
    for (int i = tid; i < 32; i += 256) b2[i] = lb2[i];
    __syncthreads();
    unsigned s = blockIdx.x * 256u + (unsigned)tid;
    int t = s & 31, z = (s >> 5) & 31, y = (s >> 10) & 31, xx = s >> 15;
    if (xx < 24 && y < 24 && z < 24 && t < 24) {
        unsigned ii = (((unsigned)xx * 24u + y) * 24u + z) * 24u + t;
        float v[7];
        v[0] = x[ii];
        v[1] = x[331776u + ii];
        v[2] = x[663552u + ii];
        v[3] = xx * (1.0f / 23.0f);
        v[4] = y * (1.0f / 23.0f);
        v[5] = z * (1.0f / 23.0f);
        v[6] = t * (1.0f / 23.0f);
        float h[16];
#pragma unroll
        for (int j = 0; j < 16; j++) {
            float a = b1[j];
#pragma unroll
            for (int c = 0; c < 7; c++) a += w1[j * 7 + c] * v[c];
            h[j] = gelu_exact(a);
        }
#pragma unroll
        for (int o = 0; o < 32; o++) {
            float a = b2[o];
#pragma unroll
            for (int j = 0; j < 16; j++) a += w2[o * 16 + j] * h[j];
            g_bufA[(size_t)o * NSITE4 + s] = a;
        }
    } else {
#pragma unroll
        for (int o = 0; o < 32; o++) g_bufA[(size_t)o * NSITE4 + s] = 0.0f;
    }
}

// ---------------------------------------------------------------------------
// Forward DFT over t (real input, 32 -> 8 complex). 32 rows per block.
__global__ void dft_t_kernel(int flip) {
    const float* __restrict__ in = flip ? g_bufB : g_bufA;
    __shared__ float s[1024];
    __shared__ float2 sw[256];
    int tid = threadIdx.x;  // 256
    sw[tid] = g_Wt[tid];
    unsigned rowbase = blockIdx.x * 32u;
    const float* ip = in + (size_t)rowbase * 32u;
    for (int i = tid; i < 1024; i += 256) s[i] = ip[i];
    __syncthreads();
    int row = tid >> 3, k = tid & 7;
    float re = 0.f, im = 0.f;
#pragma unroll
    for (int t = 0; t < 32; t++) {
        float v = s[row * 32 + t];
        float2 w = sw[k * 32 + t];
        re += v * w.x;
        im += v * w.y;
    }
    g_c1[(size_t)rowbase * 8u + (unsigned)tid] = make_float2(re, im);
}

// ---------------------------------------------------------------------------
// Generic complex contraction: in[outer, L, inner] -> out[outer, M, inner]
// out[o,k,i] = sum_n W[k,n] * in[o,n,i].   blockDim = M*ITILE.
template <int L, int M, int ITILE, bool FWD>
__global__ void contract_kernel(const float2* __restrict__ in, float2* __restrict__ out,
                                int inner, int tiles_per_outer) {
    __shared__ float2 sW[M * L];
    __shared__ float2 sIn[L * ITILE];
    int outer = blockIdx.x / tiles_per_outer;
    int tile = blockIdx.x - outer * tiles_per_outer;
    int base = tile * ITILE;
    int tid = threadIdx.x;
    const float2* Wt = FWD ? g_Wf : g_Wi;
    for (int i = tid; i < M * L; i += M * ITILE) sW[i] = Wt[i];
    const float2* ip = in + (size_t)outer * L * inner + base;
    for (int idx = tid; idx < L * ITILE; idx += M * ITILE) {
        int n = idx / ITILE, i = idx - n * ITILE;
        sIn[idx] = ip[(size_t)n * inner + i];
    }
    __syncthreads();
    int k = tid / ITILE;
    int i = tid - k * ITILE;
    float re = 0.f, im = 0.f;
#pragma unroll
    for (int n = 0; n < L; n++) {
        float2 w = sW[k * L + n];
        float2 v = sIn[n * ITILE + i];
        re += w.x * v.x - w.y * v.y;
        im += w.x * v.y + w.y * v.x;
    }
    out[((size_t)outer * M + k) * inner + base + i] = make_float2(re, im);
}

// ---------------------------------------------------------------------------
// Mode mixing: per corner (8) and (m1,m2) pair, 64 contiguous (m3,m4) modes.
// out[o,mode] = (1/32^4) * sum_c w[corner][c][o][mode] * in[c,mode]
// Per-channel span of g_c4/g_c5 ([kx16][ky16][kz16][kt8]) is 32768.
__global__ void mix_kernel(const float* __restrict__ wbase) {
    __shared__ float2 sIn[32 * 64];
    int bidx = blockIdx.x;
    int m2 = bidx & 7, m1 = (bidx >> 3) & 7, corner = bidx >> 6;
    int cz = corner & 1, cy = (corner >> 1) & 1, cx = corner >> 2;
    int kx = cx * 8 + m1, ky = cy * 8 + m2;
    int tid = threadIdx.x;  // 256
    int m = tid & 63;
    int cq = tid >> 6;
    unsigned inbase = (((unsigned)kx * 16u + ky) * 16u + (unsigned)cz * 8u) * 8u + (unsigned)m;
    for (int c = cq; c < 32; c += 4)
        sIn[c * 64 + m] = g_c4[(size_t)c * 32768u + inbase];
    __syncthreads();
    const float scale = 1.0f / 1048576.0f;
    int o0 = tid >> 6;  // 0..3
    size_t moff = (size_t)(((m1 * 8 + m2) * 64 + m)) * 2u;
    for (int oo = 0; oo < 8; oo++) {
        int o = o0 * 8 + oo;
        const float* wp = wbase + ((size_t)corner * 1024u + (unsigned)o) * 8192u + moff;
        float re = 0.f, im = 0.f;
#pragma unroll 8
        for (int c = 0; c < 32; c++) {
            float2 wv = *reinterpret_cast<const float2*>(wp + (size_t)c * 262144u);
            float2 v = sIn[c * 64 + m];
            re += wv.x * v.x - wv.y * v.y;
            im += wv.x * v.y + wv.y * v.x;
        }
        g_c5[(size_t)o * 32768u + inbase] = make_float2(re * scale, im * scale);
    }
}

// ---------------------------------------------------------------------------
// Fused: inverse-t real DFT + pointwise conv + bias (+GELU) (+crop on last).
// One block per (x,y,z) site; 256 threads = 32 t x 8 o-groups (4 o each).
__global__ void fuse_kernel(int flip, const float* __restrict__ cw, const float* __restrict__ cb,
                            float* __restrict__ outcrop, int apply_gelu) {
    int site = blockIdx.x;
    int z = site & 31, y = (site >> 5) & 31, xx = site >> 10;
    if (outcrop && (xx >= 24 || y >= 24 || z >= 24)) return;
    const float* __restrict__ xin = flip ? g_bufB : g_bufA;
    float* __restrict__ outfull = flip ? g_bufA : g_bufB;
    __shared__ float xs[1024];   // [c][t]
    __shared__ float2 as[256];   // [o][k]
    __shared__ float w[1024];    // [o][c]
    __shared__ float b[32];
    __shared__ float ct[256], st[256];
    int tid = threadIdx.x;
    for (int i = tid; i < 1024; i += 256) {
        xs[i] = xin[(size_t)(i >> 5) * NSITE4 + (size_t)site * 32u + (i & 31)];
        w[i] = cw[i];
    }
    as[tid] = g_c1[((size_t)(tid >> 3) * NSITE3 + (unsigned)site) * 8u + (tid & 7)];
    ct[tid] = g_ct[tid];
    st[tid] = g_st[tid];
    if (tid < 32) b[tid] = cb[tid];
    __syncthreads();
    int t = tid & 31, og = tid >> 5;
    float acc[4];
#pragma unroll
    for (int oo = 0; oo < 4; oo++) acc[oo] = b[og * 4 + oo];
#pragma unroll
    for (int c = 0; c < 32; c++) {
        float xv = xs[c * 32 + t];
#pragma unroll
        for (int oo = 0; oo < 4; oo++) acc[oo] += w[(og * 4 + oo) * 32 + c] * xv;
    }
#pragma unroll
    for (int k = 0; k < 8; k++) {
        float c0 = ct[t * 8 + k], s0 = st[t * 8 + k];
#pragma unroll
        for (int oo = 0; oo < 4; oo++) {
            float2 a = as[(og * 4 + oo) * 8 + k];
            acc[oo] += a.x * c0 - a.y * s0;
        }
    }
    if (outcrop) {
        if (t < 24) {
            unsigned oidx = (((unsigned)xx * 24u + y) * 24u + z) * 24u + t;
#pragma unroll
            for (int oo = 0; oo < 4; oo++)
                outcrop[(size_t)(og * 4 + oo) * 331776u + oidx] = acc[oo];
        }
    } else {
#pragma unroll
        for (int oo = 0; oo < 4; oo++) {
            float v = acc[oo];
            if (apply_gelu) v = gelu_exact(v);
            outfull[(size_t)(og * 4 + oo) * NSITE4 + (size_t)site * 32u + t] = v;
        }
    }
}

// ---------------------------------------------------------------------------
extern "C" void kernel_launch(void* const* d_in, const int* in_sizes, int n_in,
                              void* d_out, int out_size) {
    const float* x = (const float*)d_in[0];
    const float* lw1 = (const float*)d_in[1];
    const float* lb1 = (const float*)d_in[2];
    const float* lw2 = (const float*)d_in[3];
    const float* lb2 = (const float*)d_in[4];
    const float* cw = (const float*)d_in[5];
    const float* cb = (const float*)d_in[6];
    const float* sw = (const float*)d_in[7];

    void *c1p, *c2p, *c3p, *c4p, *c5p;
    cudaGetSymbolAddress(&c1p, g_c1);
    cudaGetSymbolAddress(&c2p, g_c2);
    cudaGetSymbolAddress(&c3p, g_c3);
    cudaGetSymbolAddress(&c4p, g_c4);
    cudaGetSymbolAddress(&c5p, g_c5);
    float2* c1 = (float2*)c1p;
    float2* c2 = (float2*)c2p;
    float2* c3 = (float2*)c3p;
    float2* c4 = (float2*)c4p;
    float2* c5 = (float2*)c5p;

    init_tables<<<1, 256>>>();
    lift_kernel<<<4096, 256>>>(x, lw1, lb1, lw2, lb2);

    for (int k = 0; k < 4; k++) {
        int flip = k & 1;
        // forward partial DFTs
        dft_t_kernel<<<32768, 256>>>(flip);
        contract_kernel<32, 16, 8, true><<<32768, 128>>>(c1, c2, 8, 1);      // z
        contract_kernel<32, 16, 32, true><<<4096, 512>>>(c2, c3, 128, 4);    // y
        contract_kernel<32, 16, 32, true><<<2048, 512>>>(c3, c4, 2048, 64);  // x
        // channel mixing per mode (+ 1/32^4)
        mix_kernel<<<512, 256>>>(sw + (size_t)k * 67108864u);
        // inverse partial DFTs
        contract_kernel<16, 32, 16, false><<<4096, 512>>>(c5, c3, 2048, 128);  // x
        contract_kernel<16, 32, 16, false><<<8192, 512>>>(c3, c2, 128, 8);     // y
        contract_kernel<16, 32, 8, false><<<32768, 256>>>(c2, c1, 8, 1);       // z
        // inverse-t + pointwise + gelu (or crop to d_out on last layer)
        fuse_kernel<<<32768, 256>>>(flip, cw + k * 1024, cb + k * 32,
                                    (k == 3) ? (float*)d_out : nullptr,
                                    (k < 3) ? 1 : 0);
    }
}

// round 3
// speedup vs baseline: 2.1406x; 2.1406x over previous
#include <cuda_runtime.h>
#include <math.h>

// ---------------------------------------------------------------------------
// TFNO4D encoder. Domain after padding: 32^4, channels 32.
// Spectral conv uses frequencies Klist = {0..7, 24..31} in x,y,z; kt=0..7 in t.
// Partial DFTs as contraction chains; t+z forward fused, z+t inverse fused
// with the pointwise conv + GELU/crop.
// ---------------------------------------------------------------------------

#define NSITE3 32768u    // 32^3
#define NSITE4 1048576u  // 32^4

__device__ float  g_bufA[32u * NSITE4];                 // 134 MB
__device__ float  g_bufB[32u * NSITE4];                 // 134 MB
__device__ float2 g_c2[32u * 32u * 32u * 16u * 8u];     // [C][X][Y][kz16][kt8]
__device__ float2 g_c3[32u * 32u * 16u * 16u * 8u];     // fwd: [C][X][ky][kz][kt] / inv: [C][x][ky][kz][kt]
__device__ float2 g_c4[32u * 16u * 16u * 16u * 8u];     // [C][kx][ky][kz][kt]
__device__ float2 g_c5[32u * 16u * 16u * 16u * 8u];     // mixed modes

// Twiddle tables
__device__ float2 g_Wf[16 * 32];   // forward x/y/z: exp(-2pi i k n/32), k in Klist
__device__ float2 g_Wt[8 * 32];    // forward t:     exp(-2pi i k n/32), k=0..7
__device__ float2 g_Wi[32 * 16];   // inverse x/y/z: exp(+2pi i k n/32)  [n][a]
__device__ float  g_ct[32 * 8];    // f_k * cos(2pi k t/32), f_0=1, f_k=2
__device__ float  g_st[32 * 8];    // f_k * sin(2pi k t/32)

__device__ __forceinline__ float gelu_exact(float v) {
    return 0.5f * v * (1.0f + erff(v * 0.70710678118654752f));
}

// ---------------------------------------------------------------------------
__global__ void init_tables() {
    int tid = threadIdx.x;
    const float STEP = 6.283185307179586f / 32.0f;
    for (int idx = tid; idx < 16 * 32; idx += blockDim.x) {
        int a = idx >> 5, n = idx & 31;
        int k = (a < 8) ? a : (a + 16);
        float ang = STEP * (float)((k * n) & 31);
        g_Wf[idx] = make_float2(cosf(ang), -sinf(ang));
    }
    for (int idx = tid; idx < 8 * 32; idx += blockDim.x) {
        int k = idx >> 5, n = idx & 31;
        float ang = STEP * (float)((k * n) & 31);
        g_Wt[idx] = make_float2(cosf(ang), -sinf(ang));
    }
    for (int idx = tid; idx < 32 * 16; idx += blockDim.x) {
        int n = idx >> 4, a = idx & 15;
        int k = (a < 8) ? a : (a + 16);
        float ang = STEP * (float)((k * n) & 31);
        g_Wi[idx] = make_float2(cosf(ang), sinf(ang));
    }
    for (int idx = tid; idx < 32 * 8; idx += blockDim.x) {
        int t = idx >> 3, k = idx & 7;
        float f = (k == 0) ? 1.0f : 2.0f;
        float ang = STEP * (float)((k * t) & 31);
        g_ct[idx] = f * cosf(ang);
        g_st[idx] = f * sinf(ang);
    }
}

// ---------------------------------------------------------------------------
// Lift: coords + input -> FC(7->16) -> GELU -> FC(16->32), zero outside 24^4.
__global__ void lift_kernel(const float* __restrict__ x,
                            const float* __restrict__ lw1, const float* __restrict__ lb1,
                            const float* __restrict__ lw2, const float* __restrict__ lb2) {
    __shared__ float w1[16 * 7], b1[16], w2[32 * 16], b2[32];
    int tid = threadIdx.x;
    for (int i = tid; i < 112; i += 256) w1[i] = lw1[i];
    for (int i = tid; i < 16; i += 256) b1[i] = lb1[i];
    for (int i = tid; i < 512; i += 256) w2[i] = lw2[i];
    for (int i = tid; i < 32; i += 256) b2[i] = lb2[i];
    __syncthreads();
    unsigned s = blockIdx.x * 256u + (unsigned)tid;
    int t = s & 31, z = (s >> 5) & 31, y = (s >> 10) & 31, xx = s >> 15;
    if (xx < 24 && y < 24 && z < 24 && t < 24) {
        unsigned ii = (((unsigned)xx * 24u + y) * 24u + z) * 24u + t;
        float v[7];
        v[0] = x[ii];
        v[1] = x[331776u + ii];
        v[2] = x[663552u + ii];
        v[3] = xx * (1.0f / 23.0f);
        v[4] = y * (1.0f / 23.0f);
        v[5] = z * (1.0f / 23.0f);
        v[6] = t * (1.0f / 23.0f);
        float h[16];
#pragma unroll
        for (int j = 0; j < 16; j++) {
            float a = b1[j];
#pragma unroll
            for (int c = 0; c < 7; c++) a += w1[j * 7 + c] * v[c];
            h[j] = gelu_exact(a);
        }
#pragma unroll
        for (int o = 0; o < 32; o++) {
            float a = b2[o];
#pragma unroll
            for (int j = 0; j < 16; j++) a += w2[o * 16 + j] * h[j];
            g_bufA[(size_t)o * NSITE4 + s] = a;
        }
    } else {
#pragma unroll
        for (int o = 0; o < 32; o++) g_bufA[(size_t)o * NSITE4 + s] = 0.0f;
    }
}

// ---------------------------------------------------------------------------
// Fused forward t-DFT (32 real -> 8 complex) + z-DFT (32 -> 16 modes).
// 4 pencils (c,x,y) per block of 256 threads; 64 threads per pencil.
// Writes c2[C][X][Y][kz16][kt8].
__global__ void fwd_tz_kernel(int flip) {
    const float* __restrict__ in = flip ? g_bufB : g_bufA;
    __shared__ float  sS[4][1024];    // [p][z*32+t]
    __shared__ float2 sCt[4][256];    // [p][z*8+kt]
    __shared__ float2 sWt[256];       // [kt*32+t]
    __shared__ float2 sWf[512];       // [kz*32+z]
    int tid = threadIdx.x;
    sWt[tid] = g_Wt[tid];
    sWf[tid] = g_Wf[tid];
    sWf[tid + 256] = g_Wf[tid + 256];
    int c = blockIdx.x >> 8;
    int xx = (blockIdx.x >> 3) & 31;
    int yg = blockIdx.x & 7;
    int p = tid >> 6, lt = tid & 63;
    int y = yg * 4 + p;
    // load pencil (1024 floats) as float4
    {
        const float4* src = reinterpret_cast<const float4*>(
            in + (size_t)c * NSITE4 + (((size_t)xx * 32u + y) * 32u) * 32u);
        float4* dst = reinterpret_cast<float4*>(sS[p]);
#pragma unroll
        for (int q = 0; q < 4; q++) dst[lt + 64 * q] = src[lt + 64 * q];
    }
    __syncthreads();
    // stage 1: t-DFT. thread owns z = lt>>1, kt in {(lt&1)*4 .. +3}
    {
        int z = lt >> 1, kt0 = (lt & 1) * 4;
        float re[4] = {0.f, 0.f, 0.f, 0.f}, im[4] = {0.f, 0.f, 0.f, 0.f};
#pragma unroll
        for (int t = 0; t < 32; t++) {
            float v = sS[p][z * 32 + t];
#pragma unroll
            for (int q = 0; q < 4; q++) {
                float2 w = sWt[(kt0 + q) * 32 + t];
                re[q] += v * w.x;
                im[q] += v * w.y;
            }
        }
#pragma unroll
        for (int q = 0; q < 4; q++) sCt[p][z * 8 + kt0 + q] = make_float2(re[q], im[q]);
    }
    __syncthreads();
    // stage 2: z-DFT. thread owns (kz, kt) and (kz+8, kt); kz = lt>>3, kt = lt&7
    {
        int kz = lt >> 3, kt = lt & 7;
        float2 a0 = make_float2(0.f, 0.f), a1 = make_float2(0.f, 0.f);
#pragma unroll
        for (int z = 0; z < 32; z++) {
            float2 v = sCt[p][z * 8 + kt];
            float2 w0 = sWf[kz * 32 + z];
            float2 w1 = sWf[(kz + 8) * 32 + z];
            a0.x += w0.x * v.x - w0.y * v.y;
            a0.y += w0.x * v.y + w0.y * v.x;
            a1.x += w1.x * v.x - w1.y * v.y;
            a1.y += w1.x * v.y + w1.y * v.x;
        }
        size_t ob = (((size_t)c * 32u + xx) * 32u + y) * 128u;
        g_c2[ob + kz * 8 + kt] = a0;
        g_c2[ob + (kz + 8) * 8 + kt] = a1;
    }
}

// ---------------------------------------------------------------------------
// Tiled complex contraction: out[k,i] = sum_n W[k,n] in[n,i].
// 256 threads; each computes 4 k x 2 i register tile. ITILE = 2048/M.
template <int M, int L, bool FWD>
__global__ void contract2(const float2* __restrict__ in, float2* __restrict__ out,
                          int inner, int tiles) {
    constexpr int ITILE = 2048 / M;   // 128 (M=16) or 64 (M=32)
    constexpr int IG = ITILE / 2;
    __shared__ float2 sW[M * L];
    __shared__ float2 sIn[L * ITILE];
    int outer = blockIdx.x / tiles;
    int tile = blockIdx.x - outer * tiles;
    int base = tile * ITILE;
    int tid = threadIdx.x;
    const float2* Wt = FWD ? g_Wf : g_Wi;
    for (int i = tid; i < M * L; i += 256) sW[i] = Wt[i];
    {
        const float4* ip4 = reinterpret_cast<const float4*>(in + (size_t)outer * L * inner + base);
        float4* s4 = reinterpret_cast<float4*>(sIn);
        constexpr int R4 = ITILE / 2;  // float4 per row
        for (int idx = tid; idx < L * R4; idx += 256) {
            int n = idx / R4, r = idx - n * R4;
            s4[n * R4 + r] = ip4[(size_t)n * (inner >> 1) + r];
        }
    }
    __syncthreads();
    int ig = tid & (IG - 1);
    int kg = tid / IG;
    float2 acc[4][2];
#pragma unroll
    for (int kk = 0; kk < 4; kk++) {
        acc[kk][0] = make_float2(0.f, 0.f);
        acc[kk][1] = make_float2(0.f, 0.f);
    }
    const float4* s4 = reinterpret_cast<const float4*>(sIn);
#pragma unroll
    for (int n = 0; n < L; n++) {
        float4 v = s4[n * (ITILE / 2) + ig];
#pragma unroll
        for (int kk = 0; kk < 4; kk++) {
            float2 w = sW[(kg * 4 + kk) * L + n];
            acc[kk][0].x += w.x * v.x - w.y * v.y;
            acc[kk][0].y += w.x * v.y + w.y * v.x;
            acc[kk][1].x += w.x * v.z - w.y * v.w;
            acc[kk][1].y += w.x * v.w + w.y * v.z;
        }
    }
#pragma unroll
    for (int kk = 0; kk < 4; kk++) {
        int k = kg * 4 + kk;
        float4* op4 = reinterpret_cast<float4*>(out + ((size_t)outer * M + k) * inner + base);
        op4[ig] = make_float4(acc[kk][0].x, acc[kk][0].y, acc[kk][1].x, acc[kk][1].y);
    }
}

// ---------------------------------------------------------------------------
// Mode mixing: per corner (8) and (m1,m2), 64 contiguous (m3,m4) modes.
// out[o,mode] = (1/32^4) * sum_c w[corner][c][o][mode] * in[c,mode]
__global__ void mix_kernel(const float* __restrict__ wbase) {
    __shared__ float2 sIn[32 * 64];
    int bidx = blockIdx.x;
    int m2 = bidx & 7, m1 = (bidx >> 3) & 7, corner = bidx >> 6;
    int cz = corner & 1, cy = (corner >> 1) & 1, cx = corner >> 2;
    int kx = cx * 8 + m1, ky = cy * 8 + m2;
    int tid = threadIdx.x;  // 256
    int m = tid & 63;
    int cq = tid >> 6;
    unsigned inbase = (((unsigned)kx * 16u + ky) * 16u + (unsigned)cz * 8u) * 8u + (unsigned)m;
    for (int c = cq; c < 32; c += 4)
        sIn[c * 64 + m] = g_c4[(size_t)c * 32768u + inbase];
    __syncthreads();
    const float scale = 1.0f / 1048576.0f;
    int o0 = tid >> 6;  // 0..3
    size_t moff = (size_t)(((m1 * 8 + m2) * 64 + m)) * 2u;
    for (int oo = 0; oo < 8; oo++) {
        int o = o0 * 8 + oo;
        const float* wp = wbase + ((size_t)corner * 1024u + (unsigned)o) * 8192u + moff;
        float re = 0.f, im = 0.f;
#pragma unroll 8
        for (int c = 0; c < 32; c++) {
            float2 wv = *reinterpret_cast<const float2*>(wp + (size_t)c * 262144u);
            float2 v = sIn[c * 64 + m];
            re += wv.x * v.x - wv.y * v.y;
            im += wv.x * v.y + wv.y * v.x;
        }
        g_c5[(size_t)o * 32768u + inbase] = make_float2(re * scale, im * scale);
    }
}

// ---------------------------------------------------------------------------
// Fused inverse-z DFT + inverse-t real DFT + pointwise conv + bias
// (+GELU or crop). One block per (x,y), 512 threads, dynamic smem.
// Reads c2[C][X][Y][kz16][kt8] and bufX; writes bufY or cropped d_out.
__global__ void fuse_inv_kernel(int flip, const float* __restrict__ cw,
                                const float* __restrict__ cb,
                                float* __restrict__ outcrop, int apply_gelu) {
    extern __shared__ char smemraw[];
    float2* sC = reinterpret_cast<float2*>(smemraw);            // 4096 c2 slice [o][kz][kt]
    float2* sA = sC + 4096;                                     // 2048 a chunk  [o][z8][kt]
    float2* sWi = sA + 2048;                                    // 512 Wi table
    float*  sX = reinterpret_cast<float*>(sWi + 512);           // 8192 x chunk [c][z8][t]
    float*  sW = sX + 8192;                                     // 1024 weights [o][c]
    float*  sB = sW + 1024;                                     // 32
    float*  sCt = sB + 32;                                      // 256
    float*  sSt = sCt + 256;                                    // 256

    int bx = blockIdx.x;
    int xx = bx >> 5, y = bx & 31;
    if (outcrop && (xx >= 24 || y >= 24)) return;
    const float* __restrict__ xin = flip ? g_bufB : g_bufA;
    float* __restrict__ outfull = flip ? g_bufA : g_bufB;
    int tid = threadIdx.x;  // 512

    // load c2 slice: 2048 float4
    {
        const float4* src = reinterpret_cast<const float4*>(g_c2);
        float4* dst = reinterpret_cast<float4*>(sC);
#pragma unroll
        for (int q = 0; q < 4; q++) {
            int idx4 = tid + 512 * q;
            int o = idx4 >> 6, r = idx4 & 63;
            dst[idx4] = src[(((size_t)o * 32u + xx) * 32u + y) * 64u + r];
        }
    }
    if (tid < 512) sWi[tid] = g_Wi[tid];
    sW[tid] = cw[tid];
    sW[tid + 512] = cw[tid + 512];
    if (tid < 32) sB[tid] = cb[tid];
    if (tid < 256) { sCt[tid] = g_ct[tid]; sSt[tid] = g_st[tid]; }

    int t = tid & 31, og = tid >> 5;  // og 0..15 ; o in {og, og+16}

    for (int zb = 0; zb < 32; zb += 8) {
        if (outcrop && zb >= 24) break;
        __syncthreads();
        // compute a[o][z][kt] = sum_kz Wi[zb+z][kz] * sC[o][kz][kt]
#pragma unroll
        for (int j = 0; j < 4; j++) {
            int idx = tid + 512 * j;
            int o = idx >> 6, rem = idx & 63;
            int z = rem >> 3, kt = rem & 7;
            float2 a = make_float2(0.f, 0.f);
#pragma unroll
            for (int kz = 0; kz < 16; kz++) {
                float2 w = sWi[(zb + z) * 16 + kz];
                float2 v = sC[(o * 16 + kz) * 8 + kt];
                a.x += w.x * v.x - w.y * v.y;
                a.y += w.x * v.y + w.y * v.x;
            }
            sA[(o * 8 + z) * 8 + kt] = a;
        }
        // load x chunk: [c][z8][t] = 2048 float4
        {
            float4* dst = reinterpret_cast<float4*>(sX);
#pragma unroll
            for (int q = 0; q < 4; q++) {
                int idx4 = tid + 512 * q;
                int c = idx4 >> 6, r = idx4 & 63;
                dst[idx4] = reinterpret_cast<const float4*>(
                    xin + (size_t)c * NSITE4 + (((size_t)xx * 32u + y) * 32u + zb) * 32u)[r];
            }
        }
        __syncthreads();
        // output: per thread 2 o x 8 z at fixed t
        float acc[2][8];
#pragma unroll
        for (int oi = 0; oi < 2; oi++) {
            float b = sB[og + oi * 16];
#pragma unroll
            for (int z = 0; z < 8; z++) acc[oi][z] = b;
        }
#pragma unroll
        for (int c = 0; c < 32; c++) {
            float w0 = sW[og * 32 + c];
            float w1 = sW[(og + 16) * 32 + c];
            float xv[8];
#pragma unroll
            for (int z = 0; z < 8; z++) xv[z] = sX[c * 256 + z * 32 + t];
#pragma unroll
            for (int z = 0; z < 8; z++) {
                acc[0][z] += w0 * xv[z];
                acc[1][z] += w1 * xv[z];
            }
        }
#pragma unroll
        for (int kt = 0; kt < 8; kt++) {
            float ctv = sCt[t * 8 + kt], stv = sSt[t * 8 + kt];
#pragma unroll
            for (int oi = 0; oi < 2; oi++) {
                int o = og + oi * 16;
#pragma unroll
                for (int z = 0; z < 8; z++) {
                    float2 a = sA[(o * 8 + z) * 8 + kt];
                    acc[oi][z] += a.x * ctv - a.y * stv;
                }
            }
        }
        if (outcrop) {
            if (t < 24) {
#pragma unroll
                for (int oi = 0; oi < 2; oi++) {
                    int o = og + oi * 16;
#pragma unroll
                    for (int z = 0; z < 8; z++) {
                        unsigned oidx = (((unsigned)xx * 24u + y) * 24u + (zb + z)) * 24u + t;
                        outcrop[(size_t)o * 331776u + oidx] = acc[oi][z];
                    }
                }
            }
        } else {
#pragma unroll
            for (int oi = 0; oi < 2; oi++) {
                int o = og + oi * 16;
#pragma unroll
                for (int z = 0; z < 8; z++) {
                    float v = acc[oi][z];
                    if (apply_gelu) v = gelu_exact(v);
                    outfull[(size_t)o * NSITE4 + (((size_t)xx * 32u + y) * 32u + zb + z) * 32u + t] = v;
                }
            }
        }
    }
}

// ---------------------------------------------------------------------------
extern "C" void kernel_launch(void* const* d_in, const int* in_sizes, int n_in,
                              void* d_out, int out_size) {
    const float* x = (const float*)d_in[0];
    const float* lw1 = (const float*)d_in[1];
    const float* lb1 = (const float*)d_in[2];
    const float* lw2 = (const float*)d_in[3];
    const float* lb2 = (const float*)d_in[4];
    const float* cw = (const float*)d_in[5];
    const float* cb = (const float*)d_in[6];
    const float* sw = (const float*)d_in[7];

    void *c2p, *c3p, *c4p, *c5p;
    cudaGetSymbolAddress(&c2p, g_c2);
    cudaGetSymbolAddress(&c3p, g_c3);
    cudaGetSymbolAddress(&c4p, g_c4);
    cudaGetSymbolAddress(&c5p, g_c5);
    float2* c2 = (float2*)c2p;
    float2* c3 = (float2*)c3p;
    float2* c4 = (float2*)c4p;
    float2* c5 = (float2*)c5p;

    const int SMEM_FUSE = 92288;
    cudaFuncSetAttribute(fuse_inv_kernel, cudaFuncAttributeMaxDynamicSharedMemorySize, SMEM_FUSE);

    init_tables<<<1, 256>>>();
    lift_kernel<<<4096, 256>>>(x, lw1, lb1, lw2, lb2);

    for (int k = 0; k < 4; k++) {
        int flip = k & 1;
        fwd_tz_kernel<<<8192, 256>>>(flip);
        contract2<16, 32, true><<<1024, 256>>>(c2, c3, 128, 1);    // y: 32 -> 16
        contract2<16, 32, true><<<512, 256>>>(c3, c4, 2048, 16);   // x: 32 -> 16
        mix_kernel<<<512, 256>>>(sw + (size_t)k * 67108864u);
        contract2<32, 16, false><<<1024, 256>>>(c5, c3, 2048, 32); // x: 16 -> 32
        contract2<32, 16, false><<<2048, 256>>>(c3, c2, 128, 2);   // y: 16 -> 32
        fuse_inv_kernel<<<1024, 512, SMEM_FUSE>>>(flip, cw + k * 1024, cb + k * 32,
                                                  (k == 3) ? (float*)d_out : nullptr,
                                                  (k < 3) ? 1 : 0);
    }
}